// round 7
// baseline (speedup 1.0000x reference)
#include <cuda_runtime.h>

#define BB 32
#define NN 4096
#define DD 256
#define HH 8
#define TT 28
#define ROWS (BB * NN)
#define BLK 128
#define RPB 16              // rows per block (8 threads per row)

typedef unsigned long long u64;

// ---------- packed f32x2 ops on opaque u64 register pairs ----------
__device__ __forceinline__ u64 ffma2(u64 a, u64 b, u64 c) {
    u64 d; asm("fma.rn.f32x2 %0, %1, %2, %3;" : "=l"(d) : "l"(a), "l"(b), "l"(c)); return d;
}
__device__ __forceinline__ u64 pk(float lo, float hi) {
    u64 r; asm("mov.b64 %0, {%1,%2};" : "=l"(r) : "f"(lo), "f"(hi)); return r;
}
__device__ __forceinline__ float2 upk(u64 v) {
    float2 f; asm("mov.b64 {%0,%1}, %2;" : "=f"(f.x), "=f"(f.y) : "l"(v)); return f;
}
__device__ __forceinline__ u64 dup2(float v) { return pk(v, v); }

__device__ __forceinline__ float tanhapx(float x) {
    float y; asm("tanh.approx.f32 %0, %1;" : "=f"(y) : "f"(x)); return y;
}

struct __align__(16) Smem {
    float4     xs[RPB][8];        // staged x chunk (16 rows x 32 cols), XOR swizzle (2KB)
    ulonglong2 wproj[DD / 2][8];  // [d2][L] = {Wp pair(2d2,2d2+1) of row L, Wg1 pair} (16KB)
    float      hs[RPB][8];        // h broadcast area, one float per lane (512B)
    u64        gf[RPB][TT];       // (gate, (1-gate)*decay) per row per t (3.5KB)
};

__global__ void __launch_bounds__(BLK)
horizon_kernel(const float* __restrict__ x, const float* __restrict__ last_step,
               const float* __restrict__ W_ih, const float* __restrict__ W_hh,
               const float* __restrict__ b_ih, const float* __restrict__ b_hh,
               const float* __restrict__ Wp, const float* __restrict__ bp,
               const float* __restrict__ Wo, const float* __restrict__ bo,
               const float* __restrict__ Wg1, const float* __restrict__ bg1,
               const float* __restrict__ Wg2, const float* __restrict__ bg2,
               const float* __restrict__ log_decay, float* __restrict__ out) {
    __shared__ Smem s;
    const int tid = threadIdx.x;
    const int sub = tid & 7;        // lane within row: owns gate-output lane L = sub
    const int rl  = tid >> 3;       // local row 0..15
    const int rb  = blockIdx.x * RPB;
    const int L   = sub;
    const unsigned FULL = 0xFFFFFFFFu;

    // ---------------- projection weight prep ----------------
    for (int i = tid; i < (DD / 2) * 8; i += BLK) {
        int d2 = i >> 3, Lw = i & 7;
        float2 a = __ldg((const float2*)(Wp  + Lw * DD + 2 * d2));
        float2 b = __ldg((const float2*)(Wg1 + Lw * DD + 2 * d2));
        s.wproj[d2][Lw] = make_ulonglong2(pk(a.x, a.y), pk(b.x, b.y));
    }

    // ---------------- projections: thread computes h0[L] and g1[L] (dots over d) -------
    u64 accp = 0ULL, accg = 0ULL;
#pragma unroll 1
    for (int c = 0; c < 8; c++) {
        __syncthreads();
        {   // stage 16 rows x 32 cols: exactly one float4 per thread
            int r = tid >> 3, q = tid & 7;
            float4 v = ((const float4*)(x + (size_t)(rb + r) * DD + c * 32))[q];
            s.xs[r][q ^ (r & 7)] = v;
        }
        __syncthreads();
#pragma unroll
        for (int q = 0; q < 8; q++) {
            float4 xv = s.xs[rl][q ^ (rl & 7)];
            int d2 = c * 16 + q * 2;
            ulonglong2 w0 = s.wproj[d2][sub];
            ulonglong2 w1 = s.wproj[d2 + 1][sub];
            u64 xp0 = pk(xv.x, xv.y), xp1 = pk(xv.z, xv.w);
            accp = ffma2(xp0, w0.x, accp);
            accg = ffma2(xp0, w0.y, accg);
            accp = ffma2(xp1, w1.x, accp);
            accg = ffma2(xp1, w1.y, accg);
        }
    }
    float2 pa = upk(accp), ga = upk(accg);
    float hcur = pa.x + pa.y + __ldg(bp + L);
    float g1   = fmaxf(ga.x + ga.y + __ldg(bg1 + L), 0.0f);

    const float last = last_step[rb + rl];

    // ---------------- precompute (gate, (1-gate)*decay) per t into shared --------------
    __syncwarp(FULL);
    s.hs[rl][sub] = g1;
    __syncwarp(FULL);
    {
        float4 gA = *(const float4*)&s.hs[rl][0];
        float4 gB = *(const float4*)&s.hs[rl][4];
        float edc = __expf(__ldg(log_decay));
#pragma unroll
        for (int k = 0; k < 4; k++) {
            int t = sub + 8 * k;
            if (t < TT) {
                const float4* wgr = (const float4*)(Wg2 + t * HH);
                float4 w0 = __ldg(wgr), w1 = __ldg(wgr + 1);
                float lg = __ldg(bg2 + t);
                lg = fmaf(gA.x, w0.x, lg); lg = fmaf(gA.y, w0.y, lg);
                lg = fmaf(gA.z, w0.z, lg); lg = fmaf(gA.w, w0.w, lg);
                lg = fmaf(gB.x, w1.x, lg); lg = fmaf(gB.y, w1.y, lg);
                lg = fmaf(gB.z, w1.z, lg); lg = fmaf(gB.w, w1.w, lg);
                float gate = fmaf(0.5f, tanhapx(0.5f * lg), 0.5f);
                float gd = last * __expf(-edc * (float)(t + 1));
                s.gf[rl][t] = pk(gate, (1.0f - gate) * gd);
            }
        }
    }

    // ---------------- hoist GRU weights into registers (L = sub fixed) ------------------
    // r/z weights & biases pre-scaled by 0.5 (sigmoid(v) = 0.5*tanh(v/2)+0.5)
    u64 whrz[8], whn2[4], wo2[4];
#pragma unroll
    for (int j = 0; j < 8; j++)
        whrz[j] = pk(0.5f * __ldg(W_hh + L * HH + j), 0.5f * __ldg(W_hh + (8 + L) * HH + j));
#pragma unroll
    for (int k = 0; k < 4; k++) {
        whn2[k] = pk(__ldg(W_hh + (16 + L) * HH + 2 * k), __ldg(W_hh + (16 + L) * HH + 2 * k + 1));
        wo2[k]  = pk(__ldg(Wo + 2 * k), __ldg(Wo + 2 * k + 1));
    }
    u64 wihrz = pk(0.5f * __ldg(W_ih + L), 0.5f * __ldg(W_ih + 8 + L));
    u64 brz   = pk(0.5f * (__ldg(b_ih + L) + __ldg(b_hh + L)),
                   0.5f * (__ldg(b_ih + 8 + L) + __ldg(b_hh + 8 + L)));
    float wihn = __ldg(W_ih + 16 + L);
    float bin  = __ldg(b_ih + 16 + L);
    float bhn  = __ldg(b_hh + 16 + L);
    float bo_r = __ldg(bo);

    // ---------------- GRU rollout: weights in registers, h-exchange via shared ----------
    float cur = last;
    float* outrow = out + (size_t)(rb + rl) * TT;

#pragma unroll 1
    for (int t = 0; t <= TT; t++) {
        __syncwarp(FULL);               // prior step's reads complete before overwrite
        s.hs[rl][sub] = hcur;
        __syncwarp(FULL);
        float4 fa = *(const float4*)&s.hs[rl][0];
        float4 fb = *(const float4*)&s.hs[rl][4];
        u64 p01 = pk(fa.x, fa.y), p23 = pk(fa.z, fa.w);
        u64 p45 = pk(fb.x, fb.y), p67 = pk(fb.z, fb.w);

        // pred(t-1) = Wo . h + bo (every thread computes it; SIMT makes this free)
        u64 pp = ffma2(p01, wo2[0], 0ULL);
        pp = ffma2(p23, wo2[1], pp);
        pp = ffma2(p45, wo2[2], pp);
        pp = ffma2(p67, wo2[3], pp);
        float2 pf = upk(pp);
        float pred = pf.x + pf.y + bo_r;
        if (t > 0) {
            cur = pred;
            if (((t - 1) & 7) == sub) {
                float2 gg = upk(s.gf[rl][t - 1]);
                outrow[t - 1] = fmaf(gg.x, pred, gg.y);
            }
        }
        if (t == TT) break;

        // (r,z) packed accumulator at half scale; n-gate recurrent dot via pairs
        u64 arz = ffma2(wihrz, dup2(cur), brz);
        float ain = fmaf(cur, wihn, bin);
        arz = ffma2(whrz[0], dup2(fa.x), arz);
        arz = ffma2(whrz[1], dup2(fa.y), arz);
        arz = ffma2(whrz[2], dup2(fa.z), arz);
        arz = ffma2(whrz[3], dup2(fa.w), arz);
        arz = ffma2(whrz[4], dup2(fb.x), arz);
        arz = ffma2(whrz[5], dup2(fb.y), arz);
        arz = ffma2(whrz[6], dup2(fb.z), arz);
        arz = ffma2(whrz[7], dup2(fb.w), arz);
        u64 ah4 = ffma2(whn2[0], p01, 0ULL);
        ah4 = ffma2(whn2[1], p23, ah4);
        ah4 = ffma2(whn2[2], p45, ah4);
        ah4 = ffma2(whn2[3], p67, ah4);
        float2 af = upk(ah4);
        float gh_n = af.x + af.y + bhn;

        float2 vrz = upk(arz);
        float r = fmaf(0.5f, tanhapx(vrz.x), 0.5f);
        float z = fmaf(0.5f, tanhapx(vrz.y), 0.5f);
        float n = tanhapx(fmaf(r, gh_n, ain));
        hcur = fmaf(z, hcur - n, n);    // n + z*(h-n)
    }
}

extern "C" void kernel_launch(void* const* d_in, const int* in_sizes, int n_in,
                              void* d_out, int out_size) {
    const float* x         = (const float*)d_in[0];
    const float* last_step = (const float*)d_in[1];
    const float* W_ih      = (const float*)d_in[2];
    const float* W_hh      = (const float*)d_in[3];
    const float* b_ih      = (const float*)d_in[4];
    const float* b_hh      = (const float*)d_in[5];
    const float* Wp        = (const float*)d_in[6];
    const float* bp        = (const float*)d_in[7];
    const float* Wo        = (const float*)d_in[8];
    const float* bo        = (const float*)d_in[9];
    const float* Wg1       = (const float*)d_in[10];
    const float* bg1       = (const float*)d_in[11];
    const float* Wg2       = (const float*)d_in[12];
    const float* bg2       = (const float*)d_in[13];
    const float* log_decay = (const float*)d_in[14];
    float* out = (float*)d_out;

    horizon_kernel<<<ROWS / RPB, BLK>>>(x, last_step, W_ih, W_hh, b_ih, b_hh,
                                        Wp, bp, Wo, bo, Wg1, bg1, Wg2, bg2,
                                        log_decay, out);
}

// round 8
// speedup vs baseline: 1.3259x; 1.3259x over previous
#include <cuda_runtime.h>

#define BB 32
#define NN 4096
#define DD 256
#define HH 8
#define TT 28
#define ROWS (BB * NN)
#define BLK 128
#define RPB 32              // rows per block (4 threads per row)

typedef unsigned long long u64;

// ---------- packed f32x2 ops on opaque u64 register pairs ----------
__device__ __forceinline__ u64 ffma2(u64 a, u64 b, u64 c) {
    u64 d; asm("fma.rn.f32x2 %0, %1, %2, %3;" : "=l"(d) : "l"(a), "l"(b), "l"(c)); return d;
}
__device__ __forceinline__ u64 pk(float lo, float hi) {
    u64 r; asm("mov.b64 %0, {%1,%2};" : "=l"(r) : "f"(lo), "f"(hi)); return r;
}
__device__ __forceinline__ float2 upk(u64 v) {
    float2 f; asm("mov.b64 {%0,%1}, %2;" : "=f"(f.x), "=f"(f.y) : "l"(v)); return f;
}
__device__ __forceinline__ u64 dup2(float v) { return pk(v, v); }

__device__ __forceinline__ float tanhapx(float x) {
    float y; asm("tanh.approx.f32 %0, %1;" : "=f"(y) : "f"(x)); return y;
}

#define NEG1U 0xBF800000BF800000ULL  // (-1.0f, -1.0f)

// input pre-scaled by 0.5: sigmoid(2v) = 0.5*tanh(v) + 0.5
__device__ __forceinline__ u64 sigmoid2h(u64 v) {
    float2 f = upk(v);
    return pk(fmaf(0.5f, tanhapx(f.x), 0.5f), fmaf(0.5f, tanhapx(f.y), 0.5f));
}
__device__ __forceinline__ u64 tanh2t(u64 v) {
    float2 f = upk(v);
    return pk(tanhapx(f.x), tanhapx(f.y));
}

struct Smem {
    float4     xs[RPB][8];        // staged x chunk (32 rows x 32 cols), XOR swizzle (4KB)
    ulonglong2 wprojq[DD][4];     // [d][sub]: {Wp pair(2s,2s+1), Wg1 pair(2s,2s+1)} (16KB)
    u64        gf[RPB][TT];       // precomputed (gate, (1-gate)*decay) per row per t (7KB)
};

__global__ void __launch_bounds__(BLK)
horizon_kernel(const float* __restrict__ x, const float* __restrict__ last_step,
               const float* __restrict__ W_ih, const float* __restrict__ W_hh,
               const float* __restrict__ b_ih, const float* __restrict__ b_hh,
               const float* __restrict__ Wp, const float* __restrict__ bp,
               const float* __restrict__ Wo, const float* __restrict__ bo,
               const float* __restrict__ Wg1, const float* __restrict__ bg1,
               const float* __restrict__ Wg2, const float* __restrict__ bg2,
               const float* __restrict__ log_decay, float* __restrict__ out) {
    __shared__ Smem s;
    const int tid = threadIdx.x;
    const int sub = tid & 3;        // quarter within the row (owns 2 lanes per gate)
    const int rl  = tid >> 2;       // local row 0..31
    const int rb  = blockIdx.x * RPB;
    const int L0  = 2 * sub, L1 = L0 + 1;
    const unsigned FULL = 0xFFFFFFFFu;

    // ---------------- projection weight prep ----------------
    for (int i = tid; i < DD * 4; i += BLK) {
        int d = i >> 2, ss = i & 3;
        s.wprojq[d][ss] = make_ulonglong2(
            pk(Wp[(2 * ss) * DD + d], Wp[(2 * ss + 1) * DD + d]),
            pk(Wg1[(2 * ss) * DD + d], Wg1[(2 * ss + 1) * DD + d]));
    }

    // ---------------- projections: thread owns h lanes (L0,L1) and g1 lanes (L0,L1) ------
    u64 accp = pk(bp[L0], bp[L1]);
    u64 accg = pk(bg1[L0], bg1[L1]);

#pragma unroll 1
    for (int c = 0; c < 8; c++) {
        __syncthreads();
#pragma unroll
        for (int k = 0; k < 2; k++) {
            int idx = k * BLK + tid;          // 0..255 float4s (32 rows x 8)
            int r = idx >> 3, q = idx & 7;
            float4 v = ((const float4*)(x + (size_t)(rb + r) * DD + c * 32))[q];
            s.xs[r][q ^ (r & 7)] = v;
        }
        __syncthreads();
#pragma unroll
        for (int q = 0; q < 8; q++) {
            float4 xv = s.xs[rl][q ^ (rl & 7)];
            int dbase = (c << 5) + (q << 2);
#pragma unroll
            for (int e = 0; e < 4; e++) {
                float xs_e = (e == 0) ? xv.x : (e == 1) ? xv.y : (e == 2) ? xv.z : xv.w;
                u64 xd = dup2(xs_e);
                ulonglong2 w = s.wprojq[dbase + e][sub];
                accp = ffma2(w.x, xd, accp);
                accg = ffma2(w.y, xd, accg);
            }
        }
    }

    u64 hq = accp;                     // h lanes (L0, L1)
    u64 g1q;
    {
        float2 f = upk(accg);
        g1q = pk(fmaxf(f.x, 0.0f), fmaxf(f.y, 0.0f));
    }

    const float last = last_step[rb + rl];

    // ---------------- precompute gate & decay combination per t (loop-invariant) ---------
    {
        u64 gA = __shfl_xor_sync(FULL, g1q, 1);
        u64 gB = __shfl_xor_sync(FULL, g1q, 2);
        u64 gC = __shfl_xor_sync(FULL, g1q, 3);
        float2 g0 = upk(g1q), g1v = upk(gA), g2v = upk(gB), g3v = upk(gC);
        float edc = __expf(log_decay[0]);
        int j0 = 2 * (sub ^ 0), j1 = 2 * (sub ^ 1), j2 = 2 * (sub ^ 2), j3 = 2 * (sub ^ 3);
#pragma unroll
        for (int k = 0; k < 7; k++) {
            int t = 4 * k + sub;
            const float* wr = Wg2 + t * HH;
            float lg = bg2[t];
            lg = fmaf(g0.x, wr[j0], lg);     lg = fmaf(g0.y, wr[j0 + 1], lg);
            lg = fmaf(g1v.x, wr[j1], lg);    lg = fmaf(g1v.y, wr[j1 + 1], lg);
            lg = fmaf(g2v.x, wr[j2], lg);    lg = fmaf(g2v.y, wr[j2 + 1], lg);
            lg = fmaf(g3v.x, wr[j3], lg);    lg = fmaf(g3v.y, wr[j3 + 1], lg);
            float gate = fmaf(0.5f, tanhapx(0.5f * lg), 0.5f);
            float gd = last * __expf(-edc * (float)(t + 1));
            s.gf[rl][t] = pk(gate, (1.0f - gate) * gd);
        }
    }

    // ---------------- hoist GRU weights into registers (slot-permuted to match shuffles) --
    // r/z weights & biases pre-scaled by 0.5: sigmoid(v) = 0.5*tanh(v/2)+0.5
    u64 whr[8], whz[8], whn[8], wo4[4];
#pragma unroll
    for (int p = 0; p < 4; p++) {
        int j0 = 2 * (sub ^ p);
#pragma unroll
        for (int b = 0; b < 2; b++) {
            int j = j0 + b, idx = 2 * p + b;
            whr[idx] = pk(0.5f * W_hh[L0 * HH + j],        0.5f * W_hh[L1 * HH + j]);
            whz[idx] = pk(0.5f * W_hh[(8 + L0) * HH + j],  0.5f * W_hh[(8 + L1) * HH + j]);
            whn[idx] = pk(W_hh[(16 + L0) * HH + j],        W_hh[(16 + L1) * HH + j]);
        }
        wo4[p] = pk(Wo[j0], Wo[j0 + 1]);
    }
    u64 wihr = pk(0.5f * W_ih[L0], 0.5f * W_ih[L1]);
    u64 wihz = pk(0.5f * W_ih[8 + L0], 0.5f * W_ih[8 + L1]);
    u64 wihn = pk(W_ih[16 + L0], W_ih[16 + L1]);
    u64 bsr  = pk(0.5f * (b_ih[L0] + b_hh[L0]), 0.5f * (b_ih[L1] + b_hh[L1]));
    u64 bsz  = pk(0.5f * (b_ih[8 + L0] + b_hh[8 + L0]), 0.5f * (b_ih[8 + L1] + b_hh[8 + L1]));
    u64 bain = pk(b_ih[16 + L0], b_ih[16 + L1]);
    u64 bahn = pk(b_hh[16 + L0], b_hh[16 + L1]);
    const float bo_r = bo[0];

    // ---------------- GRU rollout: 4 threads/row, weights in registers, shfl exchange -----
    float cur = last;
    float* outrow = out + (size_t)(rb + rl) * TT;

#pragma unroll 1
    for (int t = 0; t <= TT; t++) {
        // butterfly h-exchange: slot p holds lanes (2*(sub^p), +1)
        u64 h1 = __shfl_xor_sync(FULL, hq, 1);
        u64 h2 = __shfl_xor_sync(FULL, hq, 2);
        u64 h3 = __shfl_xor_sync(FULL, hq, 3);
        // pred(t-1) = Wo . h + bo  (computed locally by every thread, no reduction)
        u64 pp = ffma2(hq, wo4[0], 0ULL);
        pp = ffma2(h1, wo4[1], pp);
        pp = ffma2(h2, wo4[2], pp);
        pp = ffma2(h3, wo4[3], pp);
        float2 pf = upk(pp);
        float p = pf.x + pf.y + bo_r;
        if (t > 0) {
            cur = p;
            if (((t - 1) & 3) == sub) {
                float2 gg = upk(s.gf[rl][t - 1]);
                outrow[t - 1] = fmaf(gg.x, p, gg.y);   // gate*pred + (1-gate)*decay
            }
        }
        if (t == TT) break;

        float2 f0 = upk(hq), f1 = upk(h1), f2 = upk(h2), f3 = upk(h3);
        u64 curd = dup2(cur);
        u64 ar = ffma2(wihr, curd, bsr);
        u64 az = ffma2(wihz, curd, bsz);
        u64 ai = ffma2(wihn, curd, bain);
        u64 ah = bahn;
#define STEPJ(idx, hval) { u64 hd = dup2(hval); \
        ar = ffma2(whr[idx], hd, ar); \
        az = ffma2(whz[idx], hd, az); \
        ah = ffma2(whn[idx], hd, ah); }
        STEPJ(0, f0.x) STEPJ(1, f0.y)
        STEPJ(2, f1.x) STEPJ(3, f1.y)
        STEPJ(4, f2.x) STEPJ(5, f2.y)
        STEPJ(6, f3.x) STEPJ(7, f3.y)
#undef STEPJ
        u64 r = sigmoid2h(ar);
        u64 z = sigmoid2h(az);
        u64 n = tanh2t(ffma2(r, ah, ai));
        u64 d = ffma2(n, NEG1U, hq);     // h - n
        hq = ffma2(z, d, n);             // n + z*(h-n)
    }
}

extern "C" void kernel_launch(void* const* d_in, const int* in_sizes, int n_in,
                              void* d_out, int out_size) {
    const float* x         = (const float*)d_in[0];
    const float* last_step = (const float*)d_in[1];
    const float* W_ih      = (const float*)d_in[2];
    const float* W_hh      = (const float*)d_in[3];
    const float* b_ih      = (const float*)d_in[4];
    const float* b_hh      = (const float*)d_in[5];
    const float* Wp        = (const float*)d_in[6];
    const float* bp        = (const float*)d_in[7];
    const float* Wo        = (const float*)d_in[8];
    const float* bo        = (const float*)d_in[9];
    const float* Wg1       = (const float*)d_in[10];
    const float* bg1       = (const float*)d_in[11];
    const float* Wg2       = (const float*)d_in[12];
    const float* bg2       = (const float*)d_in[13];
    const float* log_decay = (const float*)d_in[14];
    float* out = (float*)d_out;

    horizon_kernel<<<ROWS / RPB, BLK>>>(x, last_step, W_ih, W_hh, b_ih, b_hh,
                                        Wp, bp, Wo, bo, Wg1, bg1, Wg2, bg2,
                                        log_decay, out);
}

// round 9
// speedup vs baseline: 1.5116x; 1.1400x over previous
#include <cuda_runtime.h>

#define BB 32
#define NN 4096
#define DD 256
#define HH 8
#define TT 28
#define ROWS (BB * NN)
#define BLK 128
#define RPB 32              // rows per block (4 threads per row in GRU phase)

typedef unsigned long long u64;

// ---------- packed f32x2 ops on opaque u64 register pairs ----------
__device__ __forceinline__ u64 ffma2(u64 a, u64 b, u64 c) {
    u64 d; asm("fma.rn.f32x2 %0, %1, %2, %3;" : "=l"(d) : "l"(a), "l"(b), "l"(c)); return d;
}
__device__ __forceinline__ u64 fadd2(u64 a, u64 b) {
    u64 d; asm("add.rn.f32x2 %0, %1, %2;" : "=l"(d) : "l"(a), "l"(b)); return d;
}
__device__ __forceinline__ u64 pk(float lo, float hi) {
    u64 r; asm("mov.b64 %0, {%1,%2};" : "=l"(r) : "f"(lo), "f"(hi)); return r;
}
__device__ __forceinline__ float2 upk(u64 v) {
    float2 f; asm("mov.b64 {%0,%1}, %2;" : "=f"(f.x), "=f"(f.y) : "l"(v)); return f;
}
__device__ __forceinline__ u64 dup2(float v) { return pk(v, v); }

__device__ __forceinline__ float tanhapx(float x) {
    float y; asm("tanh.approx.f32 %0, %1;" : "=f"(y) : "f"(x)); return y;
}

#define NEG1U 0xBF800000BF800000ULL  // (-1.0f, -1.0f)

// input pre-scaled by 0.5: sigmoid(2v) = 0.5*tanh(v) + 0.5
__device__ __forceinline__ u64 sigmoid2h(u64 v) {
    float2 f = upk(v);
    return pk(fmaf(0.5f, tanhapx(f.x), 0.5f), fmaf(0.5f, tanhapx(f.y), 0.5f));
}
__device__ __forceinline__ u64 tanh2t(u64 v) {
    float2 f = upk(v);
    return pk(tanhapx(f.x), tanhapx(f.y));
}

struct Smem {
    float4     xs[RPB][32];       // staged half of x: 32 rows x 128 cols (16KB)
    ulonglong2 wq[64 * 17];       // [chunk][e*4 + pg*2 + i] + 1-slot/chunk pad (17KB)
    u64        gf[RPB][TT];       // (gate, (1-gate)*decay) per row per t (7KB)
    u64        res[2][RPB][4];    // reduced projection: [pg][row][pair] (2KB)
};

__global__ void __launch_bounds__(BLK)
horizon_kernel(const float* __restrict__ x, const float* __restrict__ last_step,
               const float* __restrict__ W_ih, const float* __restrict__ W_hh,
               const float* __restrict__ b_ih, const float* __restrict__ b_hh,
               const float* __restrict__ Wp, const float* __restrict__ bp,
               const float* __restrict__ Wo, const float* __restrict__ bo,
               const float* __restrict__ Wg1, const float* __restrict__ bg1,
               const float* __restrict__ Wg2, const float* __restrict__ bg2,
               const float* __restrict__ log_decay, float* __restrict__ out) {
    __shared__ Smem s;
    const int tid = threadIdx.x;
    const int rb  = blockIdx.x * RPB;
    const unsigned FULL = 0xFFFFFFFFu;

    // projection-phase roles
    const int pg  = tid >> 6;          // 0 = Wp, 1 = Wg1
    const int rgp = (tid >> 4) & 3;    // row group (8 rows each)
    const int ds  = tid & 15;          // d-slice (chunks ds, ds+16, ds+32, ds+48)

    // ---------------- weight prep: wq[chunk*17 + e*4 + pg*2 + i] ----------------
    for (int idx = tid; idx < 64 * 16; idx += BLK) {
        int chunk = idx >> 4, r = idx & 15;
        int e = r >> 2, pgw = (r >> 1) & 1, i = r & 1;
        int d = chunk * 4 + e;
        const float* W = pgw ? Wg1 : Wp;
        s.wq[chunk * 17 + e * 4 + pgw * 2 + i] = make_ulonglong2(
            pk(W[(4 * i + 0) * DD + d], W[(4 * i + 1) * DD + d]),
            pk(W[(4 * i + 2) * DD + d], W[(4 * i + 3) * DD + d]));
    }

    // ---------------- projection: 8 rows x 4 pairs x 16-d slice per thread -------
    u64 acc[32];
#pragma unroll
    for (int i = 0; i < 32; i++) acc[i] = 0ULL;

#pragma unroll 1
    for (int cst = 0; cst < 2; cst++) {
        __syncthreads();
#pragma unroll
        for (int k = 0; k < 8; k++) {          // stage 32 rows x 128 cols, coalesced
            int f = k * BLK + tid;
            int row = f >> 5, q = f & 31;
            s.xs[row][q] = ((const float4*)(x + (size_t)(rb + row) * DD + cst * 128))[q];
        }
        __syncthreads();
#pragma unroll 1
        for (int m2 = 0; m2 < 2; m2++) {
            int chunkL = ds + 16 * m2;          // local float4 col 0..31
            int chunkG = cst * 32 + chunkL;
            ulonglong2 w[8];
#pragma unroll
            for (int e = 0; e < 4; e++) {
                w[2 * e]     = s.wq[chunkG * 17 + e * 4 + pg * 2 + 0];
                w[2 * e + 1] = s.wq[chunkG * 17 + e * 4 + pg * 2 + 1];
            }
#pragma unroll
            for (int r = 0; r < 8; r++) {
                float4 xv = s.xs[rgp * 8 + r][chunkL];
#pragma unroll
                for (int e = 0; e < 4; e++) {
                    float xe = (e == 0) ? xv.x : (e == 1) ? xv.y : (e == 2) ? xv.z : xv.w;
                    u64 xd = dup2(xe);
                    acc[r * 4 + 0] = ffma2(w[2 * e].x,     xd, acc[r * 4 + 0]);
                    acc[r * 4 + 1] = ffma2(w[2 * e].y,     xd, acc[r * 4 + 1]);
                    acc[r * 4 + 2] = ffma2(w[2 * e + 1].x, xd, acc[r * 4 + 2]);
                    acc[r * 4 + 3] = ffma2(w[2 * e + 1].y, xd, acc[r * 4 + 3]);
                }
            }
        }
    }

    // ---------------- recursive-halving shuffle reduction over the 16 d-slices ----
    // round (cnt, bit): lane with (ds&bit)==0 keeps low half, partner keeps high.
#define REDROUND(cnt, bit) { int db = ds & (bit); \
    _Pragma("unroll") \
    for (int i = 0; i < (cnt) / 2; i++) { \
        u64 snd = db ? acc[i] : acc[i + (cnt) / 2]; \
        u64 rcv = __shfl_xor_sync(FULL, snd, (bit)); \
        u64 kp  = db ? acc[i + (cnt) / 2] : acc[i]; \
        acc[i] = fadd2(kp, rcv); \
    } }
    REDROUND(32, 1)
    REDROUND(16, 2)
    REDROUND(8, 4)
    REDROUND(4, 8)
#undef REDROUND
    // ownership: row bit2=ds0, bit1=ds1, bit0=ds2; pair-group b=ds3; acc[0..1]=pairs 2b,2b+1
    {
        int r_own = 4 * (ds & 1) + 2 * ((ds >> 1) & 1) + ((ds >> 2) & 1);
        int b = (ds >> 3) & 1;
        *(ulonglong2*)&s.res[pg][rgp * 8 + r_own][2 * b] = make_ulonglong2(acc[0], acc[1]);
    }
    __syncthreads();

    // ---------------- GRU-phase roles ----------------
    const int sub = tid & 3;        // quarter within the row (owns 2 lanes per gate)
    const int rl  = tid >> 2;       // local row 0..31
    const int L0  = 2 * sub, L1 = L0 + 1;

    u64 hq = fadd2(s.res[0][rl][sub], pk(bp[L0], bp[L1]));
    u64 g1q;
    {
        float2 f = upk(fadd2(s.res[1][rl][sub], pk(bg1[L0], bg1[L1])));
        g1q = pk(fmaxf(f.x, 0.0f), fmaxf(f.y, 0.0f));
    }

    const float last = last_step[rb + rl];

    // ---------------- precompute gate & decay combination per t (loop-invariant) ---------
    {
        u64 gA = __shfl_xor_sync(FULL, g1q, 1);
        u64 gB = __shfl_xor_sync(FULL, g1q, 2);
        u64 gC = __shfl_xor_sync(FULL, g1q, 3);
        float2 g0 = upk(g1q), g1v = upk(gA), g2v = upk(gB), g3v = upk(gC);
        float edc = __expf(log_decay[0]);
        int j0 = 2 * (sub ^ 0), j1 = 2 * (sub ^ 1), j2 = 2 * (sub ^ 2), j3 = 2 * (sub ^ 3);
#pragma unroll
        for (int k = 0; k < 7; k++) {
            int t = 4 * k + sub;
            const float* wr = Wg2 + t * HH;
            float lg = bg2[t];
            lg = fmaf(g0.x, wr[j0], lg);     lg = fmaf(g0.y, wr[j0 + 1], lg);
            lg = fmaf(g1v.x, wr[j1], lg);    lg = fmaf(g1v.y, wr[j1 + 1], lg);
            lg = fmaf(g2v.x, wr[j2], lg);    lg = fmaf(g2v.y, wr[j2 + 1], lg);
            lg = fmaf(g3v.x, wr[j3], lg);    lg = fmaf(g3v.y, wr[j3 + 1], lg);
            float gate = fmaf(0.5f, tanhapx(0.5f * lg), 0.5f);
            float gd = last * __expf(-edc * (float)(t + 1));
            s.gf[rl][t] = pk(gate, (1.0f - gate) * gd);
        }
    }

    // ---------------- hoist GRU weights into registers (slot-permuted to match shuffles) --
    // r/z weights & biases pre-scaled by 0.5: sigmoid(v) = 0.5*tanh(v/2)+0.5
    u64 whr[8], whz[8], whn[8], wo4[4];
#pragma unroll
    for (int p = 0; p < 4; p++) {
        int j0 = 2 * (sub ^ p);
#pragma unroll
        for (int b = 0; b < 2; b++) {
            int j = j0 + b, idx = 2 * p + b;
            whr[idx] = pk(0.5f * W_hh[L0 * HH + j],        0.5f * W_hh[L1 * HH + j]);
            whz[idx] = pk(0.5f * W_hh[(8 + L0) * HH + j],  0.5f * W_hh[(8 + L1) * HH + j]);
            whn[idx] = pk(W_hh[(16 + L0) * HH + j],        W_hh[(16 + L1) * HH + j]);
        }
        wo4[p] = pk(Wo[j0], Wo[j0 + 1]);
    }
    u64 wihr = pk(0.5f * W_ih[L0], 0.5f * W_ih[L1]);
    u64 wihz = pk(0.5f * W_ih[8 + L0], 0.5f * W_ih[8 + L1]);
    u64 wihn = pk(W_ih[16 + L0], W_ih[16 + L1]);
    u64 bsr  = pk(0.5f * (b_ih[L0] + b_hh[L0]), 0.5f * (b_ih[L1] + b_hh[L1]));
    u64 bsz  = pk(0.5f * (b_ih[8 + L0] + b_hh[8 + L0]), 0.5f * (b_ih[8 + L1] + b_hh[8 + L1]));
    u64 bain = pk(b_ih[16 + L0], b_ih[16 + L1]);
    u64 bahn = pk(b_hh[16 + L0], b_hh[16 + L1]);
    const float bo_r = bo[0];

    // ---------------- GRU rollout: 4 threads/row, weights in registers, shfl exchange -----
    float cur = last;
    float* outrow = out + (size_t)(rb + rl) * TT;

#pragma unroll 1
    for (int t = 0; t <= TT; t++) {
        // butterfly h-exchange: slot p holds lanes (2*(sub^p), +1)
        u64 h1 = __shfl_xor_sync(FULL, hq, 1);
        u64 h2 = __shfl_xor_sync(FULL, hq, 2);
        u64 h3 = __shfl_xor_sync(FULL, hq, 3);
        // pred(t-1) = Wo . h + bo  (computed locally by every thread, no reduction)
        u64 pp = ffma2(hq, wo4[0], 0ULL);
        pp = ffma2(h1, wo4[1], pp);
        pp = ffma2(h2, wo4[2], pp);
        pp = ffma2(h3, wo4[3], pp);
        float2 pf = upk(pp);
        float p = pf.x + pf.y + bo_r;
        if (t > 0) {
            cur = p;
            if (((t - 1) & 3) == sub) {
                float2 gg = upk(s.gf[rl][t - 1]);
                outrow[t - 1] = fmaf(gg.x, p, gg.y);   // gate*pred + (1-gate)*decay
            }
        }
        if (t == TT) break;

        float2 f0 = upk(hq), f1 = upk(h1), f2 = upk(h2), f3 = upk(h3);
        u64 curd = dup2(cur);
        u64 ar = ffma2(wihr, curd, bsr);
        u64 az = ffma2(wihz, curd, bsz);
        u64 ai = ffma2(wihn, curd, bain);
        u64 ah = bahn;
#define STEPJ(idx, hval) { u64 hd = dup2(hval); \
        ar = ffma2(whr[idx], hd, ar); \
        az = ffma2(whz[idx], hd, az); \
        ah = ffma2(whn[idx], hd, ah); }
        STEPJ(0, f0.x) STEPJ(1, f0.y)
        STEPJ(2, f1.x) STEPJ(3, f1.y)
        STEPJ(4, f2.x) STEPJ(5, f2.y)
        STEPJ(6, f3.x) STEPJ(7, f3.y)
#undef STEPJ
        u64 r = sigmoid2h(ar);
        u64 z = sigmoid2h(az);
        u64 n = tanh2t(ffma2(r, ah, ai));
        u64 d = ffma2(n, NEG1U, hq);     // h - n
        hq = ffma2(z, d, n);             // n + z*(h-n)
    }
}

extern "C" void kernel_launch(void* const* d_in, const int* in_sizes, int n_in,
                              void* d_out, int out_size) {
    const float* x         = (const float*)d_in[0];
    const float* last_step = (const float*)d_in[1];
    const float* W_ih      = (const float*)d_in[2];
    const float* W_hh      = (const float*)d_in[3];
    const float* b_ih      = (const float*)d_in[4];
    const float* b_hh      = (const float*)d_in[5];
    const float* Wp        = (const float*)d_in[6];
    const float* bp        = (const float*)d_in[7];
    const float* Wo        = (const float*)d_in[8];
    const float* bo        = (const float*)d_in[9];
    const float* Wg1       = (const float*)d_in[10];
    const float* bg1       = (const float*)d_in[11];
    const float* Wg2       = (const float*)d_in[12];
    const float* bg2       = (const float*)d_in[13];
    const float* log_decay = (const float*)d_in[14];
    float* out = (float*)d_out;

    horizon_kernel<<<ROWS / RPB, BLK>>>(x, last_step, W_ih, W_hh, b_ih, b_hh,
                                        Wp, bp, Wo, bo, Wg1, bg1, Wg2, bg2,
                                        log_decay, out);
}